// round 12
// baseline (speedup 1.0000x reference)
#include <cuda_runtime.h>
#include <math.h>
#include <stdint.h>

#define NB  8
#define SEQ 2048
#define DIM 512
#define SCALE 0.04419417382415922f  // 1/sqrt(512)

// tf32-rounded copies: Qr pre-scaled, Kr, and V transposed to [b][d][j].
__device__ float g_Qr[(size_t)NB * SEQ * DIM];
__device__ float g_Kr[(size_t)NB * SEQ * DIM];
__device__ float g_Vt[(size_t)NB * DIM * SEQ];

// ---------------------------------------------------------------------------
// helpers
// ---------------------------------------------------------------------------
__device__ __forceinline__ uint32_t f2tf(float x) {
    uint32_t u;
    asm("cvt.rna.tf32.f32 %0, %1;" : "=r"(u) : "f"(x));
    return u;
}
__device__ __forceinline__ float f2tf_f(float x) {
    return __uint_as_float(f2tf(x));
}

__device__ __forceinline__ uint32_t smem_u32(const void* p) {
    uint32_t a;
    asm("{ .reg .u64 t; cvta.to.shared.u64 t, %1; cvt.u32.u64 %0, t; }"
        : "=r"(a) : "l"(p));
    return a;
}

#define CP_ASYNC16(dst_u32, src_ptr) \
    asm volatile("cp.async.cg.shared.global [%0], [%1], 16;" \
                 :: "r"(dst_u32), "l"(src_ptr) : "memory")
#define CP_COMMIT() asm volatile("cp.async.commit_group;" ::: "memory")
#define CP_WAIT1()  asm volatile("cp.async.wait_group 1;" ::: "memory")

__device__ __forceinline__ void mma_tf32(float* d, const uint32_t* a, const uint32_t* b) {
    asm volatile(
        "mma.sync.aligned.m16n8k8.row.col.f32.tf32.tf32.f32 "
        "{%0,%1,%2,%3}, {%4,%5,%6,%7}, {%8,%9}, {%0,%1,%2,%3};\n"
        : "+f"(d[0]), "+f"(d[1]), "+f"(d[2]), "+f"(d[3])
        : "r"(a[0]), "r"(a[1]), "r"(a[2]), "r"(a[3]),
          "r"(b[0]), "r"(b[1]));
}

__device__ __forceinline__ void ldsm_x4(uint32_t* d, uint32_t addr) {
    asm volatile(
        "ldmatrix.sync.aligned.m8n8.x4.shared.b16 {%0,%1,%2,%3}, [%4];"
        : "=r"(d[0]), "=r"(d[1]), "=r"(d[2]), "=r"(d[3]) : "r"(addr));
}

// ---------------------------------------------------------------------------
// Pre-pass 1: tf32 round Q (pre-scaled by SCALE) and K.
// ---------------------------------------------------------------------------
__global__ __launch_bounds__(256)
void round_qk_kernel(const float* __restrict__ Q, const float* __restrict__ K,
                     float* __restrict__ Qr, float* __restrict__ Kr) {
    const int which = blockIdx.y;
    const float* in  = which ? K : Q;
    float*       out = which ? Kr : Qr;
    const float s = which ? 1.0f : SCALE;

    size_t i = (size_t)blockIdx.x * 256 + threadIdx.x;
    float4 v = reinterpret_cast<const float4*>(in)[i];
    v.x = f2tf_f(v.x * s); v.y = f2tf_f(v.y * s);
    v.z = f2tf_f(v.z * s); v.w = f2tf_f(v.w * s);
    reinterpret_cast<float4*>(out)[i] = v;
}

// ---------------------------------------------------------------------------
// Pre-pass 2: transpose V to [b][d][j] with tf32 rounding.
// ---------------------------------------------------------------------------
__global__ __launch_bounds__(256)
void transpose_v_kernel(const float* __restrict__ V, float* __restrict__ Vt) {
    __shared__ float t[32][33];
    const int b = blockIdx.z;
    const int j0 = blockIdx.x * 32;
    const int d0 = blockIdx.y * 32;
    const int tx = threadIdx.x, ty = threadIdx.y;  // 32 x 8
    const float* v = V + (size_t)b * SEQ * DIM;
    float* o = Vt + (size_t)b * DIM * SEQ;
#pragma unroll
    for (int i = 0; i < 4; i++)
        t[ty + i * 8][tx] = f2tf_f(v[(size_t)(j0 + ty + i * 8) * DIM + d0 + tx]);
    __syncthreads();
#pragma unroll
    for (int i = 0; i < 4; i++)
        o[(size_t)(d0 + ty + i * 8) * SEQ + j0 + tx] = t[tx][ty + i * 8];
}

// ---------------------------------------------------------------------------
// Unified NT GEMM: C[m,n] = sum_k A[m,k] * B[n,k]
// 128x128 tile, BK=32, 3-stage cp.async, 256 threads (8 warps 2x4),
// warp tile 64x32, fragments via ldmatrix.
// B fragments: two n-tiles per ldmatrix.x4 (paired).
// Next-chunk cp.async issued AFTER ks=0 compute to unblock the tensor pipe.
// ---------------------------------------------------------------------------
#define G_TW 4608  // words per tile per stage: 128*36

template <int KTOT, int LDA, int LDB, int LDC>
__global__ __launch_bounds__(256, 2)
void gemm_nt_kernel(const float* __restrict__ Ag, const float* __restrict__ Bg,
                    float* __restrict__ Cg) {
    extern __shared__ __align__(16) uint32_t sh[];
    uint32_t* As = sh;                // 3 stages
    uint32_t* Bs = sh + 3 * G_TW;     // 3 stages
    const uint32_t as_b = smem_u32(As);
    const uint32_t bs_b = smem_u32(Bs);

    const int z  = blockIdx.z;
    const int i0 = blockIdx.y * 128;
    const int n0 = blockIdx.x * 128;

    const float* a = Ag + (size_t)z * SEQ * LDA + (size_t)i0 * LDA;
    const float* bp = Bg + (size_t)z * (size_t)SEQ * DIM + (size_t)n0 * LDB;
    float* out = Cg + (size_t)z * SEQ * LDC;

    const int tid  = threadIdx.x;
    const int warp = tid >> 5;
    const int lane = tid & 31;
    const int wm = (warp & 1) * 64;
    const int wn = (warp >> 1) * 32;

    // ldmatrix per-lane addresses (bytes, within a stage)
    const int lr = lane & 7;
    const int g  = lane >> 3;                   // 0..3
    // A x4: matrices = (row groups +0,+8) x (k halves 0,4)
    const uint32_t a_off = ((wm + (g & 1) * 8 + lr) * 36 + (g >> 1) * 4) * 4;
    // B paired x4: groups 0/1 = n-tile (pair base), k half 0/1;
    //              groups 2/3 = n-tile +1,        k half 0/1
    const uint32_t b_off = ((wn + (g >> 1) * 8 + lr) * 36 + (g & 1) * 4) * 4;

    // epilogue coords
    const int r = lane >> 2;
    const int c = lane & 3;

    int lrow[4], lc4[4];
#pragma unroll
    for (int t = 0; t < 4; t++) {
        int f = tid + t * 256;
        lrow[t] = f >> 3;
        lc4[t]  = f & 7;
    }

    float acc[16][4];
#pragma unroll
    for (int i = 0; i < 16; i++)
#pragma unroll
        for (int j = 0; j < 4; j++) acc[i][j] = 0.0f;

    const int NT = KTOT / 32;

#pragma unroll
    for (int pc = 0; pc < 2; pc++) {
#pragma unroll
        for (int t = 0; t < 4; t++) {
            uint32_t so = (pc * G_TW + lrow[t] * 36 + lc4[t] * 4) * 4;
            CP_ASYNC16(as_b + so, &a[(size_t)lrow[t] * LDA + pc * 32 + lc4[t] * 4]);
            CP_ASYNC16(bs_b + so, &bp[(size_t)lrow[t] * LDB + pc * 32 + lc4[t] * 4]);
        }
        CP_COMMIT();
    }

    for (int kt = 0; kt < NT; kt++) {
        const int s = kt % 3;
        CP_WAIT1();
        __syncthreads();

        const uint32_t a_s = as_b + s * (G_TW * 4) + a_off;
        const uint32_t b_s = bs_b + s * (G_TW * 4) + b_off;

        // ---- ks = 0: start the tensor pipe before issuing next loads ----
        {
            uint32_t au[4][4], bu[2][4];
#pragma unroll
            for (int mt = 0; mt < 4; mt++)
                ldsm_x4(au[mt], a_s + mt * 2304);
#pragma unroll
            for (int np = 0; np < 2; np++)
                ldsm_x4(bu[np], b_s + np * 2304);
#pragma unroll
            for (int mt = 0; mt < 4; mt++)
#pragma unroll
                for (int nt = 0; nt < 4; nt++)
                    mma_tf32(acc[mt * 4 + nt], au[mt], &bu[nt >> 1][(nt & 1) * 2]);
        }

        // ---- issue next chunk's loads (hidden behind remaining compute) ----
        if (kt + 2 < NT) {
            const int s2 = (kt + 2) % 3;
            const int k0 = (kt + 2) * 32;
#pragma unroll
            for (int t = 0; t < 4; t++) {
                uint32_t so = (s2 * G_TW + lrow[t] * 36 + lc4[t] * 4) * 4;
                CP_ASYNC16(as_b + so, &a[(size_t)lrow[t] * LDA + k0 + lc4[t] * 4]);
                CP_ASYNC16(bs_b + so, &bp[(size_t)lrow[t] * LDB + k0 + lc4[t] * 4]);
            }
        }
        CP_COMMIT();

        // ---- ks = 1..3 ----
#pragma unroll
        for (int ks = 1; ks < 4; ks++) {
            uint32_t au[4][4], bu[2][4];
#pragma unroll
            for (int mt = 0; mt < 4; mt++)
                ldsm_x4(au[mt], a_s + mt * 2304 + ks * 32);
#pragma unroll
            for (int np = 0; np < 2; np++)
                ldsm_x4(bu[np], b_s + np * 2304 + ks * 32);
#pragma unroll
            for (int mt = 0; mt < 4; mt++)
#pragma unroll
                for (int nt = 0; nt < 4; nt++)
                    mma_tf32(acc[mt * 4 + nt], au[mt], &bu[nt >> 1][(nt & 1) * 2]);
        }
    }

#pragma unroll
    for (int mt = 0; mt < 4; mt++) {
#pragma unroll
        for (int nt = 0; nt < 4; nt++) {
            float* av = acc[mt * 4 + nt];
            int row = i0 + wm + mt * 16 + r;
            int col = n0 + wn + nt * 8 + c * 2;
            float2 v0 = make_float2(av[0], av[1]);
            float2 v1 = make_float2(av[2], av[3]);
            *reinterpret_cast<float2*>(&out[(size_t)row * LDC + col]) = v0;
            *reinterpret_cast<float2*>(&out[(size_t)(row + 8) * LDC + col]) = v1;
        }
    }
}

// ---------------------------------------------------------------------------
// Softmax: one WARP per row of 2048 (register-resident, shfl reductions).
// Output rounded to tf32 for GEMM2.
// ---------------------------------------------------------------------------
__global__ __launch_bounds__(256)
void softmax_kernel(float* __restrict__ attn) {
    const int warp = threadIdx.x >> 5;
    const int lane = threadIdx.x & 31;
    const size_t row = (size_t)blockIdx.x * 8 + warp;
    float4* p4 = reinterpret_cast<float4*>(attn + row * SEQ);

    float4 v[16];
#pragma unroll
    for (int i = 0; i < 16; i++) v[i] = p4[lane + 32 * i];

    float m = -3.4e38f;
#pragma unroll
    for (int i = 0; i < 16; i++) {
        m = fmaxf(m, fmaxf(fmaxf(v[i].x, v[i].y), fmaxf(v[i].z, v[i].w)));
    }
#pragma unroll
    for (int o = 16; o > 0; o >>= 1)
        m = fmaxf(m, __shfl_xor_sync(0xffffffffu, m, o));

    float s = 0.0f;
#pragma unroll
    for (int i = 0; i < 16; i++) {
        v[i].x = __expf(v[i].x - m);
        v[i].y = __expf(v[i].y - m);
        v[i].z = __expf(v[i].z - m);
        v[i].w = __expf(v[i].w - m);
        s += (v[i].x + v[i].y) + (v[i].z + v[i].w);
    }
#pragma unroll
    for (int o = 16; o > 0; o >>= 1)
        s += __shfl_xor_sync(0xffffffffu, s, o);

    const float inv = 1.0f / s;
#pragma unroll
    for (int i = 0; i < 16; i++) {
        v[i].x = f2tf_f(v[i].x * inv);
        v[i].y = f2tf_f(v[i].y * inv);
        v[i].z = f2tf_f(v[i].z * inv);
        v[i].w = f2tf_f(v[i].w * inv);
        p4[lane + 32 * i] = v[i];
    }
}

// ---------------------------------------------------------------------------
extern "C" void kernel_launch(void* const* d_in, const int* in_sizes, int n_in,
                              void* d_out, int out_size) {
    const float* Q = (const float*)d_in[0];
    const float* K = (const float*)d_in[1];
    const float* V = (const float*)d_in[2];

    float* ctx  = (float*)d_out;                      // [8, 2048, 512]
    float* attn = ctx + (size_t)NB * SEQ * DIM;       // [8, 2048, 2048]

    float *Qr, *Kr, *Vt;
    cudaGetSymbolAddress((void**)&Qr, g_Qr);
    cudaGetSymbolAddress((void**)&Kr, g_Kr);
    cudaGetSymbolAddress((void**)&Vt, g_Vt);

    constexpr int G_SMEM = 3 * G_TW * 2 * 4;  // 110592 B
    cudaFuncSetAttribute(gemm_nt_kernel<DIM, DIM, DIM, SEQ>,
                         cudaFuncAttributeMaxDynamicSharedMemorySize, G_SMEM);
    cudaFuncSetAttribute(gemm_nt_kernel<SEQ, SEQ, SEQ, DIM>,
                         cudaFuncAttributeMaxDynamicSharedMemorySize, G_SMEM);

    // One-time side stream + events for capture-legal fork/join (no device
    // memory allocation involved; identical work recorded every call).
    static cudaStream_t s_side = nullptr;
    static cudaEvent_t s_fork = nullptr, s_join = nullptr;
    if (s_side == nullptr) {
        cudaStreamCreateWithFlags(&s_side, cudaStreamNonBlocking);
        cudaEventCreateWithFlags(&s_fork, cudaEventDisableTiming);
        cudaEventCreateWithFlags(&s_join, cudaEventDisableTiming);
    }

    const int n4 = NB * SEQ * DIM / 4;

    // Fork: transpose_v (feeds only av) runs concurrently with the qk chain.
    cudaEventRecord(s_fork, 0);
    cudaStreamWaitEvent(s_side, s_fork, 0);
    transpose_v_kernel<<<dim3(SEQ / 32, DIM / 32, NB), dim3(32, 8), 0, s_side>>>(V, Vt);
    cudaEventRecord(s_join, s_side);

    // Main chain.
    round_qk_kernel<<<dim3(n4 / 256, 2), 256>>>(Q, K, Qr, Kr);

    dim3 g1(SEQ / 128, SEQ / 128, NB);
    gemm_nt_kernel<DIM, DIM, DIM, SEQ><<<g1, 256, G_SMEM>>>(Qr, Kr, attn);

    softmax_kernel<<<NB * SEQ / 8, 256>>>(attn);

    // Join before av (needs Vt).
    cudaStreamWaitEvent(0, s_join, 0);
    dim3 g2(DIM / 128, SEQ / 128, NB);
    gemm_nt_kernel<SEQ, SEQ, SEQ, DIM><<<g2, 256, G_SMEM>>>(attn, Vt, ctx);
}

// round 13
// speedup vs baseline: 1.0545x; 1.0545x over previous
#include <cuda_runtime.h>
#include <math.h>
#include <stdint.h>

#define NB  8
#define SEQ 2048
#define DIM 512
#define SCALE 0.04419417382415922f  // 1/sqrt(512)

// Scratch: tf32-rounded Qr (pre-scaled), Kr, V transposed; exp-weights,
// per-(row, jtile) partial sums, and reciprocal row sums.
__device__ float g_Qr[(size_t)NB * SEQ * DIM];
__device__ float g_Kr[(size_t)NB * SEQ * DIM];
__device__ float g_Vt[(size_t)NB * DIM * SEQ];
__device__ float g_Ew[(size_t)NB * SEQ * SEQ];      // tf32(exp(logit))
__device__ float g_Ps[(size_t)NB * SEQ * 16];       // partial sums per j-tile
__device__ float g_Rs[(size_t)NB * SEQ];            // 1 / row sum

// ---------------------------------------------------------------------------
// helpers
// ---------------------------------------------------------------------------
__device__ __forceinline__ uint32_t f2tf(float x) {
    uint32_t u;
    asm("cvt.rna.tf32.f32 %0, %1;" : "=r"(u) : "f"(x));
    return u;
}
__device__ __forceinline__ float f2tf_f(float x) {
    return __uint_as_float(f2tf(x));
}

__device__ __forceinline__ uint32_t smem_u32(const void* p) {
    uint32_t a;
    asm("{ .reg .u64 t; cvta.to.shared.u64 t, %1; cvt.u32.u64 %0, t; }"
        : "=r"(a) : "l"(p));
    return a;
}

#define CP_ASYNC16(dst_u32, src_ptr) \
    asm volatile("cp.async.cg.shared.global [%0], [%1], 16;" \
                 :: "r"(dst_u32), "l"(src_ptr) : "memory")
#define CP_COMMIT() asm volatile("cp.async.commit_group;" ::: "memory")
#define CP_WAIT1()  asm volatile("cp.async.wait_group 1;" ::: "memory")

__device__ __forceinline__ void mma_tf32(float* d, const uint32_t* a, const uint32_t* b) {
    asm volatile(
        "mma.sync.aligned.m16n8k8.row.col.f32.tf32.tf32.f32 "
        "{%0,%1,%2,%3}, {%4,%5,%6,%7}, {%8,%9}, {%0,%1,%2,%3};\n"
        : "+f"(d[0]), "+f"(d[1]), "+f"(d[2]), "+f"(d[3])
        : "r"(a[0]), "r"(a[1]), "r"(a[2]), "r"(a[3]),
          "r"(b[0]), "r"(b[1]));
}

__device__ __forceinline__ void ldsm_x4(uint32_t* d, uint32_t addr) {
    asm volatile(
        "ldmatrix.sync.aligned.m8n8.x4.shared.b16 {%0,%1,%2,%3}, [%4];"
        : "=r"(d[0]), "=r"(d[1]), "=r"(d[2]), "=r"(d[3]) : "r"(addr));
}

// ---------------------------------------------------------------------------
// Pre-pass 1: tf32 round Q (pre-scaled by SCALE) and K.
// ---------------------------------------------------------------------------
__global__ __launch_bounds__(256)
void round_qk_kernel(const float* __restrict__ Q, const float* __restrict__ K,
                     float* __restrict__ Qr, float* __restrict__ Kr) {
    const int which = blockIdx.y;
    const float* in  = which ? K : Q;
    float*       out = which ? Kr : Qr;
    const float s = which ? 1.0f : SCALE;

    size_t i = (size_t)blockIdx.x * 256 + threadIdx.x;
    float4 v = reinterpret_cast<const float4*>(in)[i];
    v.x = f2tf_f(v.x * s); v.y = f2tf_f(v.y * s);
    v.z = f2tf_f(v.z * s); v.w = f2tf_f(v.w * s);
    reinterpret_cast<float4*>(out)[i] = v;
}

// ---------------------------------------------------------------------------
// Pre-pass 2: transpose V to [b][d][j] with tf32 rounding.
// ---------------------------------------------------------------------------
__global__ __launch_bounds__(256)
void transpose_v_kernel(const float* __restrict__ V, float* __restrict__ Vt) {
    __shared__ float t[32][33];
    const int b = blockIdx.z;
    const int j0 = blockIdx.x * 32;
    const int d0 = blockIdx.y * 32;
    const int tx = threadIdx.x, ty = threadIdx.y;  // 32 x 8
    const float* v = V + (size_t)b * SEQ * DIM;
    float* o = Vt + (size_t)b * DIM * SEQ;
#pragma unroll
    for (int i = 0; i < 4; i++)
        t[ty + i * 8][tx] = f2tf_f(v[(size_t)(j0 + ty + i * 8) * DIM + d0 + tx]);
    __syncthreads();
#pragma unroll
    for (int i = 0; i < 4; i++)
        o[(size_t)(d0 + ty + i * 8) * SEQ + j0 + tx] = t[tx][ty + i * 8];
}

// ---------------------------------------------------------------------------
// Unified NT GEMM: C[m,n] = sum_k A[m,k] * B[n,k]
// MODE 0 (qk): epilogue computes tf32(exp(acc)), stores to C (=Ew), emits
//   deterministic per-(row, jtile) partial sums into Ps.
// MODE 1 (av): epilogue scales each output row by rs[row].
// 128x128 tile, BK=32, 3-stage cp.async, 256 threads (8 warps 2x4),
// warp tile 64x32, ldmatrix fragments (B paired x4).
// ---------------------------------------------------------------------------
#define G_TW 4608  // words per tile per stage: 128*36

template <int KTOT, int LDA, int LDB, int LDC, int MODE>
__global__ __launch_bounds__(256, 2)
void gemm_nt_kernel(const float* __restrict__ Ag, const float* __restrict__ Bg,
                    float* __restrict__ Cg, float* __restrict__ Ps,
                    const float* __restrict__ rs) {
    extern __shared__ __align__(16) uint32_t sh[];
    uint32_t* As = sh;                // 3 stages
    uint32_t* Bs = sh + 3 * G_TW;     // 3 stages
    const uint32_t as_b = smem_u32(As);
    const uint32_t bs_b = smem_u32(Bs);

    const int z  = blockIdx.z;
    const int i0 = blockIdx.y * 128;
    const int n0 = blockIdx.x * 128;

    const float* a = Ag + (size_t)z * SEQ * LDA + (size_t)i0 * LDA;
    const float* bp = Bg + (size_t)z * (size_t)SEQ * DIM + (size_t)n0 * LDB;
    float* out = Cg + (size_t)z * SEQ * LDC;

    const int tid  = threadIdx.x;
    const int warp = tid >> 5;
    const int lane = tid & 31;
    const int wm = (warp & 1) * 64;
    const int wn = (warp >> 1) * 32;

    const int lr = lane & 7;
    const int g  = lane >> 3;
    const uint32_t a_off = ((wm + (g & 1) * 8 + lr) * 36 + (g >> 1) * 4) * 4;
    const uint32_t b_off = ((wn + (g >> 1) * 8 + lr) * 36 + (g & 1) * 4) * 4;

    const int r = lane >> 2;
    const int c = lane & 3;

    int lrow[4], lc4[4];
#pragma unroll
    for (int t = 0; t < 4; t++) {
        int f = tid + t * 256;
        lrow[t] = f >> 3;
        lc4[t]  = f & 7;
    }

    float acc[16][4];
#pragma unroll
    for (int i = 0; i < 16; i++)
#pragma unroll
        for (int j = 0; j < 4; j++) acc[i][j] = 0.0f;

    const int NT = KTOT / 32;

#pragma unroll
    for (int pc = 0; pc < 2; pc++) {
#pragma unroll
        for (int t = 0; t < 4; t++) {
            uint32_t so = (pc * G_TW + lrow[t] * 36 + lc4[t] * 4) * 4;
            CP_ASYNC16(as_b + so, &a[(size_t)lrow[t] * LDA + pc * 32 + lc4[t] * 4]);
            CP_ASYNC16(bs_b + so, &bp[(size_t)lrow[t] * LDB + pc * 32 + lc4[t] * 4]);
        }
        CP_COMMIT();
    }

    for (int kt = 0; kt < NT; kt++) {
        const int s = kt % 3;
        CP_WAIT1();
        __syncthreads();

        const uint32_t a_s = as_b + s * (G_TW * 4) + a_off;
        const uint32_t b_s = bs_b + s * (G_TW * 4) + b_off;

        {   // ks = 0 first, so the tensor pipe starts before new loads issue
            uint32_t au[4][4], bu[2][4];
#pragma unroll
            for (int mt = 0; mt < 4; mt++)
                ldsm_x4(au[mt], a_s + mt * 2304);
#pragma unroll
            for (int np = 0; np < 2; np++)
                ldsm_x4(bu[np], b_s + np * 2304);
#pragma unroll
            for (int mt = 0; mt < 4; mt++)
#pragma unroll
                for (int nt = 0; nt < 4; nt++)
                    mma_tf32(acc[mt * 4 + nt], au[mt], &bu[nt >> 1][(nt & 1) * 2]);
        }

        if (kt + 2 < NT) {
            const int s2 = (kt + 2) % 3;
            const int k0 = (kt + 2) * 32;
#pragma unroll
            for (int t = 0; t < 4; t++) {
                uint32_t so = (s2 * G_TW + lrow[t] * 36 + lc4[t] * 4) * 4;
                CP_ASYNC16(as_b + so, &a[(size_t)lrow[t] * LDA + k0 + lc4[t] * 4]);
                CP_ASYNC16(bs_b + so, &bp[(size_t)lrow[t] * LDB + k0 + lc4[t] * 4]);
            }
        }
        CP_COMMIT();

#pragma unroll
        for (int ks = 1; ks < 4; ks++) {
            uint32_t au[4][4], bu[2][4];
#pragma unroll
            for (int mt = 0; mt < 4; mt++)
                ldsm_x4(au[mt], a_s + mt * 2304 + ks * 32);
#pragma unroll
            for (int np = 0; np < 2; np++)
                ldsm_x4(bu[np], b_s + np * 2304 + ks * 32);
#pragma unroll
            for (int mt = 0; mt < 4; mt++)
#pragma unroll
                for (int nt = 0; nt < 4; nt++)
                    mma_tf32(acc[mt * 4 + nt], au[mt], &bu[nt >> 1][(nt & 1) * 2]);
        }
    }

    if (MODE == 0) {
        // qk epilogue: e = tf32(exp(logit)); store + deterministic row sums.
        float sumL[4] = {0, 0, 0, 0}, sumH[4] = {0, 0, 0, 0};
#pragma unroll
        for (int mt = 0; mt < 4; mt++) {
#pragma unroll
            for (int nt = 0; nt < 4; nt++) {
                float* av = acc[mt * 4 + nt];
                float e0 = f2tf_f(__expf(av[0]));
                float e1 = f2tf_f(__expf(av[1]));
                float e2 = f2tf_f(__expf(av[2]));
                float e3 = f2tf_f(__expf(av[3]));
                sumL[mt] += e0 + e1;
                sumH[mt] += e2 + e3;
                int row = i0 + wm + mt * 16 + r;
                int col = n0 + wn + nt * 8 + c * 2;
                *reinterpret_cast<float2*>(&out[(size_t)row * LDC + col]) =
                    make_float2(e0, e1);
                *reinterpret_cast<float2*>(&out[(size_t)(row + 8) * LDC + col]) =
                    make_float2(e2, e3);
            }
        }
        // reduce over the 4-lane c-group (shfl stays within the group)
#pragma unroll
        for (int mt = 0; mt < 4; mt++) {
            sumL[mt] += __shfl_xor_sync(0xffffffffu, sumL[mt], 1);
            sumL[mt] += __shfl_xor_sync(0xffffffffu, sumL[mt], 2);
            sumH[mt] += __shfl_xor_sync(0xffffffffu, sumH[mt], 1);
            sumH[mt] += __shfl_xor_sync(0xffffffffu, sumH[mt], 2);
        }
        float* red = reinterpret_cast<float*>(sh);  // reuse stage smem: [4][128]
        __syncthreads();
        if (c == 0) {
#pragma unroll
            for (int mt = 0; mt < 4; mt++) {
                red[(warp >> 1) * 128 + wm + mt * 16 + r]     = sumL[mt];
                red[(warp >> 1) * 128 + wm + mt * 16 + r + 8] = sumH[mt];
            }
        }
        __syncthreads();
        if (tid < 128) {
            float tot = red[tid] + red[128 + tid] + red[256 + tid] + red[384 + tid];
            Ps[((size_t)z * SEQ + i0 + tid) * 16 + blockIdx.x] = tot;
        }
    } else {
        // av epilogue: scale each output row by rs[row].
#pragma unroll
        for (int mt = 0; mt < 4; mt++) {
            int row = i0 + wm + mt * 16 + r;
            float invL = rs[(size_t)z * SEQ + row];
            float invH = rs[(size_t)z * SEQ + row + 8];
#pragma unroll
            for (int nt = 0; nt < 4; nt++) {
                float* av = acc[mt * 4 + nt];
                int col = n0 + wn + nt * 8 + c * 2;
                *reinterpret_cast<float2*>(&out[(size_t)row * LDC + col]) =
                    make_float2(av[0] * invL, av[1] * invL);
                *reinterpret_cast<float2*>(&out[(size_t)(row + 8) * LDC + col]) =
                    make_float2(av[2] * invH, av[3] * invH);
            }
        }
    }
}

// ---------------------------------------------------------------------------
// Row sums: rs[row] = 1 / sum over 16 j-tile partials.
// ---------------------------------------------------------------------------
__global__ __launch_bounds__(256)
void rowsum_kernel(const float* __restrict__ Ps, float* __restrict__ rs) {
    int row = blockIdx.x * 256 + threadIdx.x;   // 16384 rows total
    const float* p = Ps + (size_t)row * 16;
    float s = 0.0f;
#pragma unroll
    for (int i = 0; i < 16; i++) s += p[i];
    rs[row] = 1.0f / s;
}

// ---------------------------------------------------------------------------
// Normalize: weights[i,j] = Ew[i,j] * rs[i]  (runs concurrent with av).
// One warp per row, 8 float4 per lane.
// ---------------------------------------------------------------------------
__global__ __launch_bounds__(256)
void normalize_kernel(const float* __restrict__ Ew, const float* __restrict__ rs,
                      float* __restrict__ w) {
    const int warp = threadIdx.x >> 5;
    const int lane = threadIdx.x & 31;
    const size_t row = (size_t)blockIdx.x * 8 + warp;
    const float4* in = reinterpret_cast<const float4*>(Ew + row * SEQ);
    float4* outp = reinterpret_cast<float4*>(w + row * SEQ);
    const float inv = rs[row];
#pragma unroll
    for (int i = 0; i < 16; i++) {
        float4 v = in[lane + 32 * i];
        v.x *= inv; v.y *= inv; v.z *= inv; v.w *= inv;
        outp[lane + 32 * i] = v;
    }
}

// ---------------------------------------------------------------------------
extern "C" void kernel_launch(void* const* d_in, const int* in_sizes, int n_in,
                              void* d_out, int out_size) {
    const float* Q = (const float*)d_in[0];
    const float* K = (const float*)d_in[1];
    const float* V = (const float*)d_in[2];

    float* ctx  = (float*)d_out;                      // [8, 2048, 512]
    float* attn = ctx + (size_t)NB * SEQ * DIM;       // [8, 2048, 2048]

    float *Qr, *Kr, *Vt, *Ew, *Ps, *Rs;
    cudaGetSymbolAddress((void**)&Qr, g_Qr);
    cudaGetSymbolAddress((void**)&Kr, g_Kr);
    cudaGetSymbolAddress((void**)&Vt, g_Vt);
    cudaGetSymbolAddress((void**)&Ew, g_Ew);
    cudaGetSymbolAddress((void**)&Ps, g_Ps);
    cudaGetSymbolAddress((void**)&Rs, g_Rs);

    constexpr int G_SMEM = 3 * G_TW * 2 * 4;  // 110592 B
    cudaFuncSetAttribute(gemm_nt_kernel<DIM, DIM, DIM, SEQ, 0>,
                         cudaFuncAttributeMaxDynamicSharedMemorySize, G_SMEM);
    cudaFuncSetAttribute(gemm_nt_kernel<SEQ, SEQ, SEQ, DIM, 1>,
                         cudaFuncAttributeMaxDynamicSharedMemorySize, G_SMEM);

    static cudaStream_t s_side = nullptr;
    static cudaEvent_t s_fork = nullptr, s_vt = nullptr, s_sum = nullptr,
                       s_norm = nullptr;
    if (s_side == nullptr) {
        cudaStreamCreateWithFlags(&s_side, cudaStreamNonBlocking);
        cudaEventCreateWithFlags(&s_fork, cudaEventDisableTiming);
        cudaEventCreateWithFlags(&s_vt, cudaEventDisableTiming);
        cudaEventCreateWithFlags(&s_sum, cudaEventDisableTiming);
        cudaEventCreateWithFlags(&s_norm, cudaEventDisableTiming);
    }

    const int n4 = NB * SEQ * DIM / 4;

    // Fork side stream: V transpose (feeds av only).
    cudaEventRecord(s_fork, 0);
    cudaStreamWaitEvent(s_side, s_fork, 0);
    transpose_v_kernel<<<dim3(SEQ / 32, DIM / 32, NB), dim3(32, 8), 0, s_side>>>(V, Vt);
    cudaEventRecord(s_vt, s_side);

    // Main chain: round -> qk(+exp, partial sums) -> rowsum.
    round_qk_kernel<<<dim3(n4 / 256, 2), 256>>>(Q, K, Qr, Kr);

    dim3 g1(SEQ / 128, SEQ / 128, NB);
    gemm_nt_kernel<DIM, DIM, DIM, SEQ, 0><<<g1, 256, G_SMEM>>>(
        Qr, Kr, Ew, Ps, nullptr);

    rowsum_kernel<<<NB * SEQ / 256, 256>>>(Ps, Rs);
    cudaEventRecord(s_sum, 0);

    // Side: normalize weights output concurrent with av.
    cudaStreamWaitEvent(s_side, s_sum, 0);
    normalize_kernel<<<NB * SEQ / 8, 256, 0, s_side>>>(Ew, Rs, attn);
    cudaEventRecord(s_norm, s_side);

    // Main: av (needs Vt + Rs), then join normalize before graph end.
    cudaStreamWaitEvent(0, s_vt, 0);
    dim3 g2(DIM / 128, SEQ / 128, NB);
    gemm_nt_kernel<SEQ, SEQ, SEQ, DIM, 1><<<g2, 256, G_SMEM>>>(
        Ew, Vt, ctx, nullptr, Rs);
    cudaStreamWaitEvent(0, s_norm, 0);
}